// round 11
// baseline (speedup 1.0000x reference)
#include <cuda_runtime.h>
#include <cstdint>

// Problem constants: B=64, S=512, A=8, D=128, C=1024
#define PB  64
#define PS  512
#define PA  8
#define PD  128

#define LEN_BLOCKS 64   // first LEN_BLOCKS blocks compute candidate_len
#define CPB 64          // candidates per gather block
#define ROW_BYTES (PD * 4)   // 512

// ---- bulk-copy / mbarrier PTX helpers ----
__device__ __forceinline__ unsigned smem_addr(const void* p) {
    return (unsigned)__cvta_generic_to_shared(p);
}
__device__ __forceinline__ void mbar_init(void* mbar, unsigned count) {
    asm volatile("mbarrier.init.shared.b64 [%0], %1;"
                 :: "r"(smem_addr(mbar)), "r"(count) : "memory");
}
__device__ __forceinline__ void mbar_expect_tx(void* mbar, unsigned bytes) {
    asm volatile("mbarrier.arrive.expect_tx.shared.b64 _, [%0], %1;"
                 :: "r"(smem_addr(mbar)), "r"(bytes) : "memory");
}
__device__ __forceinline__ void mbar_wait(void* mbar, unsigned parity) {
    asm volatile(
        "{\n\t.reg .pred P1;\n\t"
        "WAIT_LOOP_%=:\n\t"
        "mbarrier.try_wait.parity.acquire.cta.shared::cta.b64 P1, [%0], %1, 0x989680;\n\t"
        "@P1 bra.uni WAIT_DONE_%=;\n\t"
        "bra.uni WAIT_LOOP_%=;\n\t"
        "WAIT_DONE_%=:\n\t}"
        :: "r"(smem_addr(mbar)), "r"(parity) : "memory");
}
__device__ __forceinline__ void bulk_g2s(void* sdst, const void* gsrc,
                                         unsigned bytes, void* mbar) {
    asm volatile(
        "cp.async.bulk.shared::cluster.global.mbarrier::complete_tx::bytes "
        "[%0], [%1], %2, [%3];"
        :: "r"(smem_addr(sdst)), "l"(gsrc), "r"(bytes), "r"(smem_addr(mbar))
        : "memory");
}
__device__ __forceinline__ void bulk_s2g(void* gdst, const void* ssrc,
                                         unsigned bytes) {
    asm volatile(
        "cp.async.bulk.global.shared::cta.bulk_group [%0], [%1], %2;"
        :: "l"(gdst), "r"(smem_addr(ssrc)), "r"(bytes) : "memory");
}
__device__ __forceinline__ void bulk_commit() {
    asm volatile("cp.async.bulk.commit_group;" ::: "memory");
}
__device__ __forceinline__ void bulk_wait0() {
    asm volatile("cp.async.bulk.wait_group 0;" ::: "memory");
}
__device__ __forceinline__ void fence_proxy_async_cta() {
    asm volatile("fence.proxy.async.shared::cta;" ::: "memory");
}

// ---------------------------------------------------------------------------
// blocks [0,64):  candidate_len per batch (independent role, reads inputs).
// blocks [64,..): gather — mask is exactly 0/1, so each output row is either
//   a verbatim 512B copy of a word_repr row or zeros. Both directions go
//   through the bulk-copy engine (G2S w/ mbarrier, S2G w/ bulk_group); the
//   per-thread LSU path carries only the tiny index/side-output traffic.
// ---------------------------------------------------------------------------
__global__ void __launch_bounds__(256)
cand_kernel(const float*  __restrict__ word_repr,
            const int*    __restrict__ anchor_cls,
            const int*    __restrict__ anchor_loc,
            const int*    __restrict__ cand_idx,
            float*        __restrict__ out,
            long long off_label,
            long long off_mask,
            long long off_loc,
            long long off_len,
            long long off_scalar,   // -1 if absent
            float scalar_val,
            int BC, int C)
{
    if (blockIdx.x < LEN_BLOCKS) {
        // ---- len role ----
        __shared__ int rsm[8];
        int batch = blockIdx.x;
        int base  = batch * C;

        int sum = 0;
        for (int i = threadIdx.x; i < C; i += blockDim.x) {
            int c = base + i;
            int b = cand_idx[3 * c + 0];
            int w = cand_idx[3 * c + 1];
            int a = cand_idx[3 * c + 2];
            long long flat = (((long long)b * PS + w) * PA + a);
            int2 loc = *reinterpret_cast<const int2*>(anchor_loc + flat * 2);
            sum += (loc.x != loc.y) ? 1 : 0;
        }
        #pragma unroll
        for (int o = 16; o > 0; o >>= 1)
            sum += __shfl_down_sync(0xFFFFFFFFu, sum, o);

        int lane = threadIdx.x & 31;
        int wid  = threadIdx.x >> 5;
        if (lane == 0) rsm[wid] = sum;
        __syncthreads();
        if (threadIdx.x == 0) {
            int total = 0;
            #pragma unroll
            for (int i = 0; i < 8; i++) total += rsm[i];
            __stcs(out + off_len + batch, fmaxf((float)total, 1.0f));
            if (batch == 0 && off_scalar >= 0)
                __stcs(out + off_scalar, scalar_val);
        }
        return;
    }

    // ---- gather role ----
    __shared__ __align__(128) float s_rows[CPB][PD];   // 32 KB staging
    __shared__ __align__(128) float s_zero[PD];        // zero row for mask==0
    __shared__ long long s_flat[CPB];
    __shared__ int       s_m[CPB];
    __shared__ float s_label[CPB], s_maskv[CPB], s_locx[CPB], s_locy[CPB];
    __shared__ __align__(8) unsigned long long s_mbar;

    int tid = threadIdx.x;
    int cb  = (blockIdx.x - LEN_BLOCKS) * CPB;

    // Per-candidate metadata (threads 0..63).
    if (tid < CPB) {
        int c = cb + tid;
        int b = cand_idx[3 * c + 0];
        int w = cand_idx[3 * c + 1];
        int a = cand_idx[3 * c + 2];
        long long flat = (((long long)b * PS + w) * PA + a);
        int2 loc = *reinterpret_cast<const int2*>(anchor_loc + flat * 2);
        int  cls = anchor_cls[flat];
        int  m   = (loc.x != loc.y) ? 1 : 0;
        s_flat[tid]  = flat;
        s_m[tid]     = m;
        s_label[tid] = (float)cls;
        s_maskv[tid] = (float)m;
        s_locx[tid]  = (float)loc.x;
        s_locy[tid]  = (float)loc.y;
    }
    if (tid < PD) s_zero[tid] = 0.0f;
    if (tid == 0) mbar_init(&s_mbar, 1);
    fence_proxy_async_cta();      // make zero-row STS visible to async proxy
    __syncthreads();

    // Thread 0 issues all G2S bulk copies against one mbarrier.
    if (tid == 0) {
        unsigned n1 = 0;
        #pragma unroll 4
        for (int i = 0; i < CPB; i++) n1 += (unsigned)s_m[i];
        mbar_expect_tx(&s_mbar, n1 * ROW_BYTES);
        for (int i = 0; i < CPB; i++) {
            if (s_m[i])
                bulk_g2s(&s_rows[i][0], word_repr + s_flat[i] * PD,
                         ROW_BYTES, &s_mbar);
        }
    }

    // Overlap the wait: flush small outputs now (data is in SMEM post-sync).
    if (tid < CPB) {
        __stcs(out + off_label + cb + tid, s_label[tid]);
        __stcs(out + off_mask  + cb + tid, s_maskv[tid]);
    }
    if (tid < 2 * CPB) {
        float v = (tid & 1) ? s_locy[tid >> 1] : s_locx[tid >> 1];
        __stcs(out + off_loc + 2 * (long long)cb + tid, v);
    }

    // Wait for all gathered rows.
    mbar_wait(&s_mbar, 0);

    // Threads 0..63 each issue one S2G bulk copy (zero row if mask==0).
    if (tid < CPB) {
        const float* src = s_m[tid] ? &s_rows[tid][0] : &s_zero[0];
        bulk_s2g(out + (long long)(cb + tid) * PD, src, ROW_BYTES);
        bulk_commit();
        bulk_wait0();   // reads from smem must finish before block exit
    }
}

// ---------------------------------------------------------------------------
// Host launcher
// ---------------------------------------------------------------------------
extern "C" void kernel_launch(void* const* d_in, const int* in_sizes, int n_in,
                              void* d_out, int out_size)
{
    const float* word_repr  = (const float*)d_in[0];  // (B,S,A,D) fp32
    const int*   anchor_cls = (const int*)d_in[1];    // (B,S,A)   int32
    const int*   anchor_loc = (const int*)d_in[2];    // (B,S,A,2) int32
    const int*   cand_idx   = (const int*)d_in[3];    // (B*C, 3)  int32
    float* out = (float*)d_out;

    int BC = in_sizes[3] / 3;          // 65536
    int C  = BC / PB;                  // 1024

    // Output tuple layout (reference return order):
    //   repr (B*C*D) | label (B*C) | [num (1)] | len (B) | mask (B*C) | loc (B*C*2)
    long long n_repr = (long long)BC * PD;
    long long total_with_scalar = n_repr + BC + 1 + PB + BC + 2LL * BC;

    long long off_label = n_repr;
    long long off_scalar, off_len;
    if ((long long)out_size >= total_with_scalar) {
        off_scalar = off_label + BC;
        off_len    = off_scalar + 1;
    } else {
        off_scalar = -1;
        off_len    = off_label + BC;
    }
    long long off_mask = off_len + PB;
    long long off_loc  = off_mask + BC;

    int threads = 256;
    int blocks  = LEN_BLOCKS + (BC + CPB - 1) / CPB;   // 64 + 1024
    cand_kernel<<<blocks, threads>>>(word_repr, anchor_cls, anchor_loc,
                                     cand_idx, out,
                                     off_label, off_mask, off_loc,
                                     off_len, off_scalar,
                                     (float)C, BC, C);
}

// round 12
// speedup vs baseline: 1.4874x; 1.4874x over previous
#include <cuda_runtime.h>
#include <cstdint>

// Problem constants: B=64, S=512, A=8, D=128, C=1024
#define PB  64
#define PS  512
#define PA  8
#define PD  128

#define LEN_BLOCKS 64   // first LEN_BLOCKS blocks compute candidate_len
#define ITER 8          // candidates per warp
#define CPB 64          // candidates per gather block (8 warps * 8)
#define ROW_BYTES (PD * 4)   // 512

// ---- bulk-copy / mbarrier PTX helpers ----
__device__ __forceinline__ unsigned smem_addr(const void* p) {
    return (unsigned)__cvta_generic_to_shared(p);
}
__device__ __forceinline__ void mbar_init(void* mbar, unsigned count) {
    asm volatile("mbarrier.init.shared.b64 [%0], %1;"
                 :: "r"(smem_addr(mbar)), "r"(count) : "memory");
}
__device__ __forceinline__ void mbar_expect_tx(void* mbar, unsigned bytes) {
    asm volatile("mbarrier.arrive.expect_tx.shared.b64 _, [%0], %1;"
                 :: "r"(smem_addr(mbar)), "r"(bytes) : "memory");
}
__device__ __forceinline__ void mbar_wait(void* mbar, unsigned parity) {
    asm volatile(
        "{\n\t.reg .pred P1;\n\t"
        "WAIT_LOOP_%=:\n\t"
        "mbarrier.try_wait.parity.acquire.cta.shared::cta.b64 P1, [%0], %1, 0x989680;\n\t"
        "@P1 bra.uni WAIT_DONE_%=;\n\t"
        "bra.uni WAIT_LOOP_%=;\n\t"
        "WAIT_DONE_%=:\n\t}"
        :: "r"(smem_addr(mbar)), "r"(parity) : "memory");
}
__device__ __forceinline__ void bulk_g2s(void* sdst, const void* gsrc,
                                         unsigned bytes, void* mbar) {
    asm volatile(
        "cp.async.bulk.shared::cluster.global.mbarrier::complete_tx::bytes "
        "[%0], [%1], %2, [%3];"
        :: "r"(smem_addr(sdst)), "l"(gsrc), "r"(bytes), "r"(smem_addr(mbar))
        : "memory");
}
__device__ __forceinline__ void bulk_s2g(void* gdst, const void* ssrc,
                                         unsigned bytes) {
    asm volatile(
        "cp.async.bulk.global.shared::cta.bulk_group [%0], [%1], %2;"
        :: "l"(gdst), "r"(smem_addr(ssrc)), "r"(bytes) : "memory");
}
__device__ __forceinline__ void bulk_commit() {
    asm volatile("cp.async.bulk.commit_group;" ::: "memory");
}
__device__ __forceinline__ void bulk_wait0() {
    asm volatile("cp.async.bulk.wait_group 0;" ::: "memory");
}
__device__ __forceinline__ void fence_proxy_async_cta() {
    asm volatile("fence.proxy.async.shared::cta;" ::: "memory");
}

// ---------------------------------------------------------------------------
// blocks [0,64):  candidate_len per batch (independent role, reads inputs).
// blocks [64,..): gather via bulk-copy engine with DISTRIBUTED issue:
//   per-warp mbarrier; each warp's lane 0 issues its 8 G2S row copies; after
//   the warp's barrier flips, lanes 0..7 each issue one S2G (zero row for
//   mask==0). Payload never touches LDG/STG/FFMA — pure copy engine.
// ---------------------------------------------------------------------------
__global__ void __launch_bounds__(256)
cand_kernel(const float*  __restrict__ word_repr,
            const int*    __restrict__ anchor_cls,
            const int*    __restrict__ anchor_loc,
            const int*    __restrict__ cand_idx,
            float*        __restrict__ out,
            long long off_label,
            long long off_mask,
            long long off_loc,
            long long off_len,
            long long off_scalar,   // -1 if absent
            float scalar_val,
            int BC, int C)
{
    if (blockIdx.x < LEN_BLOCKS) {
        // ---- len role ----
        __shared__ int rsm[8];
        int batch = blockIdx.x;
        int base  = batch * C;

        int sum = 0;
        for (int i = threadIdx.x; i < C; i += blockDim.x) {
            int c = base + i;
            int b = cand_idx[3 * c + 0];
            int w = cand_idx[3 * c + 1];
            int a = cand_idx[3 * c + 2];
            long long flat = (((long long)b * PS + w) * PA + a);
            int2 loc = *reinterpret_cast<const int2*>(anchor_loc + flat * 2);
            sum += (loc.x != loc.y) ? 1 : 0;
        }
        #pragma unroll
        for (int o = 16; o > 0; o >>= 1)
            sum += __shfl_down_sync(0xFFFFFFFFu, sum, o);

        int lane = threadIdx.x & 31;
        int wid  = threadIdx.x >> 5;
        if (lane == 0) rsm[wid] = sum;
        __syncthreads();
        if (threadIdx.x == 0) {
            int total = 0;
            #pragma unroll
            for (int i = 0; i < 8; i++) total += rsm[i];
            __stcs(out + off_len + batch, fmaxf((float)total, 1.0f));
            if (batch == 0 && off_scalar >= 0)
                __stcs(out + off_scalar, scalar_val);
        }
        return;
    }

    // ---- gather role ----
    __shared__ __align__(128) float s_rows[CPB][PD];   // 32 KB staging
    __shared__ __align__(128) float s_zero[PD];        // zero row
    __shared__ __align__(8) unsigned long long s_mbar[8];  // one per warp
    __shared__ float s_label[CPB], s_maskv[CPB], s_locx[CPB], s_locy[CPB];

    int tid  = threadIdx.x;
    int wid  = tid >> 5;
    int lane = tid & 31;
    int cb   = (blockIdx.x - LEN_BLOCKS) * CPB;
    int c0   = cb + wid * ITER;       // this warp's first candidate

    // --- metadata: one coalesced 96B idx load per warp + shuffles ---
    int val = 0;
    if (lane < 3 * ITER) val = cand_idx[3 * c0 + lane];
    int bb = __shfl_sync(0xFFFFFFFFu, val, (lane < 8) ? 3 * lane + 0 : 0);
    int ww = __shfl_sync(0xFFFFFFFFu, val, (lane < 8) ? 3 * lane + 1 : 0);
    int aa = __shfl_sync(0xFFFFFFFFu, val, (lane < 8) ? 3 * lane + 2 : 0);
    long long myflat = (((long long)bb * PS + ww) * PA + aa);
    int flat_lo = (int)(myflat & 0xFFFFFFFFll);
    int flat_hi = (int)(myflat >> 32);

    int mym = 0;
    if (lane < ITER) {
        int2 loc = *reinterpret_cast<const int2*>(anchor_loc + myflat * 2);
        int  cls = anchor_cls[myflat];
        mym = (loc.x != loc.y) ? 1 : 0;
        int l = wid * ITER + lane;
        s_label[l] = (float)cls;
        s_maskv[l] = (float)mym;
        s_locx[l]  = (float)loc.x;
        s_locy[l]  = (float)loc.y;
    }
    unsigned mbits = __ballot_sync(0xFFFFFFFFu, mym) & 0xFFu;

    // zero row + per-warp mbarrier init
    if (tid < PD) s_zero[tid] = 0.0f;
    if (lane == 0) mbar_init(&s_mbar[wid], 1);
    fence_proxy_async_cta();
    __syncthreads();   // zero row + mbar visible block-wide before async use

    // --- lane 0 of each warp issues its warp's G2S bulk copies ---
    if (lane == 0) {
        unsigned n1 = __popc(mbits);
        mbar_expect_tx(&s_mbar[wid], n1 * ROW_BYTES);
    }
    #pragma unroll
    for (int i = 0; i < ITER; i++) {
        int lo = __shfl_sync(0xFFFFFFFFu, flat_lo, i);
        int hi = __shfl_sync(0xFFFFFFFFu, flat_hi, i);
        if (lane == 0 && (mbits >> i) & 1) {
            long long fl = ((long long)hi << 32) | (unsigned int)lo;
            bulk_g2s(&s_rows[wid * ITER + i][0], word_repr + fl * PD,
                     ROW_BYTES, &s_mbar[wid]);
        }
    }

    // Overlap: coalesced flush of small outputs while TMA copies run.
    __syncthreads();
    if (tid < CPB) {
        __stcs(out + off_label + cb + tid, s_label[tid]);
        __stcs(out + off_mask  + cb + tid, s_maskv[tid]);
    }
    if (tid < 2 * CPB) {
        float v = (tid & 1) ? s_locy[tid >> 1] : s_locx[tid >> 1];
        __stcs(out + off_loc + 2 * (long long)cb + tid, v);
    }

    // --- wait for this warp's rows, then lanes 0..7 issue S2G copies ---
    mbar_wait(&s_mbar[wid], 0);
    if (lane < ITER) {
        int c = c0 + lane;
        const float* src = mym ? &s_rows[wid * ITER + lane][0] : &s_zero[0];
        bulk_s2g(out + (long long)c * PD, src, ROW_BYTES);
        bulk_commit();
        bulk_wait0();   // SMEM reads must finish before block exit
    }
}

// ---------------------------------------------------------------------------
// Host launcher
// ---------------------------------------------------------------------------
extern "C" void kernel_launch(void* const* d_in, const int* in_sizes, int n_in,
                              void* d_out, int out_size)
{
    const float* word_repr  = (const float*)d_in[0];  // (B,S,A,D) fp32
    const int*   anchor_cls = (const int*)d_in[1];    // (B,S,A)   int32
    const int*   anchor_loc = (const int*)d_in[2];    // (B,S,A,2) int32
    const int*   cand_idx   = (const int*)d_in[3];    // (B*C, 3)  int32
    float* out = (float*)d_out;

    int BC = in_sizes[3] / 3;          // 65536
    int C  = BC / PB;                  // 1024

    // Output tuple layout (reference return order):
    //   repr (B*C*D) | label (B*C) | [num (1)] | len (B) | mask (B*C) | loc (B*C*2)
    long long n_repr = (long long)BC * PD;
    long long total_with_scalar = n_repr + BC + 1 + PB + BC + 2LL * BC;

    long long off_label = n_repr;
    long long off_scalar, off_len;
    if ((long long)out_size >= total_with_scalar) {
        off_scalar = off_label + BC;
        off_len    = off_scalar + 1;
    } else {
        off_scalar = -1;
        off_len    = off_label + BC;
    }
    long long off_mask = off_len + PB;
    long long off_loc  = off_mask + BC;

    int threads = 256;
    int blocks  = LEN_BLOCKS + (BC + CPB - 1) / CPB;   // 64 + 1024
    cand_kernel<<<blocks, threads>>>(word_repr, anchor_cls, anchor_loc,
                                     cand_idx, out,
                                     off_label, off_mask, off_loc,
                                     off_len, off_scalar,
                                     (float)C, BC, C);
}